// round 2
// baseline (speedup 1.0000x reference)
#include <cuda_runtime.h>
#include <math.h>

#define B_  4
#define C_  64
#define H_  192
#define W_  192
#define OH_ 384
#define OW_ 384
#define E_  4

__device__ __forceinline__ float gelu_exact(float x) {
    return 0.5f * x * (1.0f + erff(x * 0.7071067811865476f));
}

// ---------------------------------------------------------------------------
// Single fused kernel.
// Prologue (per block): evaluate the per-pixel MLP at the 4 parity variants
// (scale is exactly 2, so coord features take 4 distinct values), compute
// routing+offset, and FOLD routing into the expert weights:
//   WcvT[v][c].r = sum_e rw_v[e] * weight_compress[e][r][c]
//   WevT[v][c].r = sum_e rw_v[e] * weight_expand  [e][c][r]
// Main loop: per output pixel, bilinear 4-tap gather + rank-4 dynamic
// compress/expand with the folded per-variant weights.
// grid = (3, 384, 4), block = 128 threads (one output pixel each).
// ---------------------------------------------------------------------------
__global__ void __launch_bounds__(128)
fused_upsampler(const float* __restrict__ x,
                const float* __restrict__ wc_g, const float* __restrict__ we_g,
                const float* __restrict__ w1,  const float* __restrict__ b1,
                const float* __restrict__ w2,  const float* __restrict__ b2,
                const float* __restrict__ rww, const float* __restrict__ rwb,
                const float* __restrict__ ofw, const float* __restrict__ ofb,
                float* __restrict__ out) {
    __shared__ float emb1[4][64];
    __shared__ float emb2[4][64];
    __shared__ float rws[4][4];
    __shared__ float offs[4][2];
    __shared__ float4 WcvT[4][64];
    __shared__ float4 WevT[4][64];

    int t = threadIdx.x;
    int j = t & 63;

    // ---- stage 1: first 1x1 conv + gelu, variants v and v+2 per thread ----
    #pragma unroll
    for (int vv = 0; vv < 2; vv++) {
        int v = (t >> 6) + 2 * vv;
        int py = v >> 1, px = v & 1;
        // scale = 2 exactly
        float chv = ((float)py + 0.5f) * 0.5f;
        float coor_h = chv - floorf(chv + 1e-6f) - 0.5f;
        float cwv = ((float)px + 0.5f) * 0.5f;
        float coor_w = cwv - floorf(cwv + 1e-6f) - 0.5f;
        float a = b1[j];
        a = fmaf(0.5f,   w1[j * 4 + 0], a);
        a = fmaf(0.5f,   w1[j * 4 + 1], a);
        a = fmaf(coor_h, w1[j * 4 + 2], a);
        a = fmaf(coor_w, w1[j * 4 + 3], a);
        emb1[v][j] = gelu_exact(a);
    }
    __syncthreads();

    // ---- stage 2: second 1x1 conv + gelu ----
    #pragma unroll
    for (int vv = 0; vv < 2; vv++) {
        int v = (t >> 6) + 2 * vv;
        float acc = b2[j];
        #pragma unroll 16
        for (int i = 0; i < 64; i++) acc = fmaf(emb1[v][i], w2[j * 64 + i], acc);
        emb2[v][j] = gelu_exact(acc);
    }
    __syncthreads();

    // ---- routing (16 dots) + offsets (8 dots) ----
    if (t < 16) {
        int v = t >> 2, e = t & 3;
        float s = rwb[e];
        for (int i = 0; i < 64; i++) s = fmaf(emb2[v][i], rww[e * 64 + i], s);
        rws[v][e] = 1.0f / (1.0f + expf(-s));
    } else if (t < 24) {
        int idx = t - 16, v = idx >> 1, d = idx & 1;
        float s = ofb[d];
        for (int i = 0; i < 64; i++) s = fmaf(emb2[v][i], ofw[d * 64 + i], s);
        offs[v][d] = s;
    }
    __syncthreads();

    // ---- fold routing into expert weights (1024 items, 8 per thread) ----
    for (int i = t; i < 1024; i += 128) {
        int v = i >> 8, c = (i >> 2) & 63, r = i & 3;
        float r0 = rws[v][0], r1 = rws[v][1], r2 = rws[v][2], r3 = rws[v][3];
        float sc = r0 * wc_g[0 * 256 + r * 64 + c];
        sc = fmaf(r1, wc_g[1 * 256 + r * 64 + c], sc);
        sc = fmaf(r2, wc_g[2 * 256 + r * 64 + c], sc);
        sc = fmaf(r3, wc_g[3 * 256 + r * 64 + c], sc);
        ((float*)&WcvT[v][c])[r] = sc;
        float se = r0 * we_g[0 * 256 + c * 4 + r];
        se = fmaf(r1, we_g[1 * 256 + c * 4 + r], se);
        se = fmaf(r2, we_g[2 * 256 + c * 4 + r], se);
        se = fmaf(r3, we_g[3 * 256 + c * 4 + r], se);
        ((float*)&WevT[v][c])[r] = se;
    }
    __syncthreads();

    // ---- main: one output pixel per thread ----
    int b  = blockIdx.z;
    int oy = blockIdx.y;
    int ox = blockIdx.x * 128 + t;
    int v  = ((oy & 1) << 1) | (ox & 1);
    float offx = offs[v][0], offy = offs[v][1];

    const float inv_wm1 = 2.0f / (float)(W_ - 1);
    const float inv_hm1 = 2.0f / (float)(H_ - 1);
    float gx = (((float)ox + 0.5f) * 0.5f - 0.5f) * inv_wm1 - 1.0f + offx * inv_wm1;
    float gy = (((float)oy + 0.5f) * 0.5f - 0.5f) * inv_hm1 - 1.0f + offy * inv_hm1;
    float ixf = (gx + 1.0f) * ((float)W_ * 0.5f) - 0.5f;
    float iyf = (gy + 1.0f) * ((float)H_ * 0.5f) - 0.5f;
    float x0f = floorf(ixf), x1f = x0f + 1.0f;
    float y0f = floorf(iyf), y1f = y0f + 1.0f;
    float wx1 = ixf - x0f, wx0 = 1.0f - wx1;
    float wy1 = iyf - y0f, wy0 = 1.0f - wy1;
    float vx0 = (x0f >= 0.0f && x0f <= (float)(W_ - 1)) ? 1.0f : 0.0f;
    float vx1 = (x1f >= 0.0f && x1f <= (float)(W_ - 1)) ? 1.0f : 0.0f;
    float vy0 = (y0f >= 0.0f && y0f <= (float)(H_ - 1)) ? 1.0f : 0.0f;
    float vy1 = (y1f >= 0.0f && y1f <= (float)(H_ - 1)) ? 1.0f : 0.0f;
    float w00 = wy0 * wx0 * vy0 * vx0;
    float w01 = wy0 * wx1 * vy0 * vx1;
    float w10 = wy1 * wx0 * vy1 * vx0;
    float w11 = wy1 * wx1 * vy1 * vx1;
    int xi0 = min(max((int)x0f, 0), W_ - 1);
    int xi1 = min(max((int)x1f, 0), W_ - 1);
    int yi0 = min(max((int)y0f, 0), H_ - 1);
    int yi1 = min(max((int)y1f, 0), H_ - 1);
    int o00 = yi0 * W_ + xi0, o01 = yi0 * W_ + xi1;
    int o10 = yi1 * W_ + xi0, o11 = yi1 * W_ + xi1;

    const float* xb = x + (size_t)b * C_ * H_ * W_;

    float fea[64];
    float m0 = 0.0f, m1 = 0.0f, m2 = 0.0f, m3 = 0.0f;

    // pass 1: bilinear gather + mid accumulation (folded compress weights)
    #pragma unroll
    for (int c = 0; c < 64; c++) {
        const float* p = xb + c * (H_ * W_);
        float f = w00 * __ldg(p + o00);
        f = fmaf(w01, __ldg(p + o01), f);
        f = fmaf(w10, __ldg(p + o10), f);
        f = fmaf(w11, __ldg(p + o11), f);
        fea[c] = f;
        float4 a = WcvT[v][c];
        m0 = fmaf(a.x, f, m0);
        m1 = fmaf(a.y, f, m1);
        m2 = fmaf(a.z, f, m2);
        m3 = fmaf(a.w, f, m3);
    }

    // pass 2: expand + residual (folded expand weights)
    float* op = out + (size_t)b * C_ * OH_ * OW_ + (size_t)oy * OW_ + ox;
    #pragma unroll
    for (int c = 0; c < 64; c++) {
        float4 bw = WevT[v][c];
        float acc = fea[c];
        acc = fmaf(bw.x, m0, acc);
        acc = fmaf(bw.y, m1, acc);
        acc = fmaf(bw.z, m2, acc);
        acc = fmaf(bw.w, m3, acc);
        op[(size_t)c * (OH_ * OW_)] = acc;
    }
}

extern "C" void kernel_launch(void* const* d_in, const int* in_sizes, int n_in,
                              void* d_out, int out_size) {
    const float* x    = (const float*)d_in[0];
    const float* wc   = (const float*)d_in[1];
    const float* we   = (const float*)d_in[2];
    const float* w1   = (const float*)d_in[3];
    const float* b1   = (const float*)d_in[4];
    const float* w2   = (const float*)d_in[5];
    const float* b2   = (const float*)d_in[6];
    const float* rww  = (const float*)d_in[7];
    const float* rwb  = (const float*)d_in[8];
    const float* ofw  = (const float*)d_in[9];
    const float* ofb  = (const float*)d_in[10];
    float* out = (float*)d_out;

    dim3 grid(3, OH_, B_);
    fused_upsampler<<<grid, 128>>>(x, wc, we, w1, b1, w2, b2,
                                   rww, rwb, ofw, ofb, out);
}

// round 3
// speedup vs baseline: 3.9389x; 3.9389x over previous
#include <cuda_runtime.h>
#include <math.h>

#define B_  4
#define C_  64
#define H_  192
#define W_  192
#define OH_ 384
#define OW_ 384

// Folded per-parity-variant weights (computed once by prep_kernel):
//  g_Wcv[v*64+c].r = sum_e rw_v[e] * weight_compress[e][r][c]
//  g_Wev[v*64+c].r = sum_e rw_v[e] * weight_expand  [e][c][r]
__device__ float4 g_Wcv[4 * 64];
__device__ float4 g_Wev[4 * 64];
__device__ float  g_offs[4][2];

__device__ __forceinline__ float gelu_exact(float x) {
    return 0.5f * x * (1.0f + erff(x * 0.7071067811865476f));
}

// ---------------------------------------------------------------------------
// Kernel A (1 block, 256 threads): evaluate the coord-MLP at the 4 parity
// variants (scale == 2 exactly), routing + offsets, fold routing into the
// expert weights, write to device globals.
// ---------------------------------------------------------------------------
__global__ void __launch_bounds__(256)
prep_kernel(const float* __restrict__ wc_g, const float* __restrict__ we_g,
            const float* __restrict__ w1,  const float* __restrict__ b1,
            const float* __restrict__ w2,  const float* __restrict__ b2,
            const float* __restrict__ rww, const float* __restrict__ rwb,
            const float* __restrict__ ofw, const float* __restrict__ ofb) {
    __shared__ float emb1[4][64];
    __shared__ float emb2[4][64];
    __shared__ float rws[4][4];

    int t = threadIdx.x;
    int v = t >> 6;        // variant (bit1 = oy parity, bit0 = ox parity)
    int j = t & 63;

    {
        int py = v >> 1, px = v & 1;
        float chv = ((float)py + 0.5f) * 0.5f;
        float coor_h = chv - floorf(chv + 1e-6f) - 0.5f;
        float cwv = ((float)px + 0.5f) * 0.5f;
        float coor_w = cwv - floorf(cwv + 1e-6f) - 0.5f;
        float a = b1[j];
        a = fmaf(0.5f,   w1[j * 4 + 0], a);
        a = fmaf(0.5f,   w1[j * 4 + 1], a);
        a = fmaf(coor_h, w1[j * 4 + 2], a);
        a = fmaf(coor_w, w1[j * 4 + 3], a);
        emb1[v][j] = gelu_exact(a);
    }
    __syncthreads();

    {
        float acc = b2[j];
        #pragma unroll 16
        for (int i = 0; i < 64; i++) acc = fmaf(emb1[v][i], w2[j * 64 + i], acc);
        emb2[v][j] = gelu_exact(acc);
    }
    __syncthreads();

    // 24 dot products (4 variants x (4 routing + 2 offset)), warp per dot.
    // 8 warps -> 3 rounds. Lane l sums 2 elements, shfl-reduce.
    int wid = t >> 5, lane = t & 31;
    for (int d = wid; d < 24; d += 8) {
        int dv = d / 6, k = d % 6;           // k: 0..3 routing e, 4..5 offset dim
        const float* wrow = (k < 4) ? (rww + k * 64) : (ofw + (k - 4) * 64);
        float s = emb2[dv][lane] * wrow[lane]
                + emb2[dv][lane + 32] * wrow[lane + 32];
        #pragma unroll
        for (int o = 16; o > 0; o >>= 1) s += __shfl_down_sync(0xffffffffu, s, o);
        if (lane == 0) {
            if (k < 4) rws[dv][k] = 1.0f / (1.0f + expf(-(s + rwb[k])));
            else       g_offs[dv][k - 4] = s + ofb[k - 4];
        }
    }
    __syncthreads();

    // Fold: 2048 outputs, 8 per thread.
    for (int i = t; i < 2048; i += 256) {
        int m = i >> 10;                 // 0 = compress, 1 = expand
        int v2 = (i >> 8) & 3, c = (i >> 2) & 63, r = i & 3;
        float r0 = rws[v2][0], r1 = rws[v2][1], r2 = rws[v2][2], r3 = rws[v2][3];
        if (m == 0) {
            float s = r0 * wc_g[0 * 256 + r * 64 + c];
            s = fmaf(r1, wc_g[1 * 256 + r * 64 + c], s);
            s = fmaf(r2, wc_g[2 * 256 + r * 64 + c], s);
            s = fmaf(r3, wc_g[3 * 256 + r * 64 + c], s);
            ((float*)&g_Wcv[v2 * 64 + c])[r] = s;
        } else {
            float s = r0 * we_g[0 * 256 + c * 4 + r];
            s = fmaf(r1, we_g[1 * 256 + c * 4 + r], s);
            s = fmaf(r2, we_g[2 * 256 + c * 4 + r], s);
            s = fmaf(r3, we_g[3 * 256 + c * 4 + r], s);
            ((float*)&g_Wev[v2 * 64 + c])[r] = s;
        }
    }
}

// ---------------------------------------------------------------------------
// Kernel B: fused bilinear gather + rank-4 dynamic compress/expand with the
// pre-folded per-variant weights. grid = (3, 384, 4), block = 128.
// ---------------------------------------------------------------------------
__global__ void __launch_bounds__(128)
upsample_kernel(const float* __restrict__ x, float* __restrict__ out) {
    __shared__ float4 Wcv[4][64];
    __shared__ float4 Wev[4][64];
    __shared__ float offs[4][2];

    int t = threadIdx.x;
    // Coalesced load of folded weights: 512 float4s, 4 per thread.
    #pragma unroll
    for (int i = 0; i < 2; i++) {
        ((float4*)Wcv)[t + i * 128] = g_Wcv[t + i * 128];
        ((float4*)Wev)[t + i * 128] = g_Wev[t + i * 128];
    }
    if (t < 8) ((float*)offs)[t] = ((const float*)g_offs)[t];
    __syncthreads();

    int b  = blockIdx.z;
    int oy = blockIdx.y;
    int ox = blockIdx.x * 128 + t;
    int v  = ((oy & 1) << 1) | (ox & 1);
    float offx = offs[v][0], offy = offs[v][1];

    const float inv_wm1 = 2.0f / (float)(W_ - 1);
    const float inv_hm1 = 2.0f / (float)(H_ - 1);
    float gx = (((float)ox + 0.5f) * 0.5f - 0.5f) * inv_wm1 - 1.0f + offx * inv_wm1;
    float gy = (((float)oy + 0.5f) * 0.5f - 0.5f) * inv_hm1 - 1.0f + offy * inv_hm1;
    float ixf = (gx + 1.0f) * ((float)W_ * 0.5f) - 0.5f;
    float iyf = (gy + 1.0f) * ((float)H_ * 0.5f) - 0.5f;
    float x0f = floorf(ixf), x1f = x0f + 1.0f;
    float y0f = floorf(iyf), y1f = y0f + 1.0f;
    float wx1 = ixf - x0f, wx0 = 1.0f - wx1;
    float wy1 = iyf - y0f, wy0 = 1.0f - wy1;
    float vx0 = (x0f >= 0.0f && x0f <= (float)(W_ - 1)) ? 1.0f : 0.0f;
    float vx1 = (x1f >= 0.0f && x1f <= (float)(W_ - 1)) ? 1.0f : 0.0f;
    float vy0 = (y0f >= 0.0f && y0f <= (float)(H_ - 1)) ? 1.0f : 0.0f;
    float vy1 = (y1f >= 0.0f && y1f <= (float)(H_ - 1)) ? 1.0f : 0.0f;
    float w00 = wy0 * wx0 * vy0 * vx0;
    float w01 = wy0 * wx1 * vy0 * vx1;
    float w10 = wy1 * wx0 * vy1 * vx0;
    float w11 = wy1 * wx1 * vy1 * vx1;
    int xi0 = min(max((int)x0f, 0), W_ - 1);
    int xi1 = min(max((int)x1f, 0), W_ - 1);
    int yi0 = min(max((int)y0f, 0), H_ - 1);
    int yi1 = min(max((int)y1f, 0), H_ - 1);
    int o00 = yi0 * W_ + xi0, o01 = yi0 * W_ + xi1;
    int o10 = yi1 * W_ + xi0, o11 = yi1 * W_ + xi1;

    const float* xb = x + (size_t)b * C_ * H_ * W_;

    float fea[64];
    float m0 = 0.0f, m1 = 0.0f, m2 = 0.0f, m3 = 0.0f;

    #pragma unroll
    for (int c = 0; c < 64; c++) {
        const float* p = xb + c * (H_ * W_);
        float f = w00 * __ldg(p + o00);
        f = fmaf(w01, __ldg(p + o01), f);
        f = fmaf(w10, __ldg(p + o10), f);
        f = fmaf(w11, __ldg(p + o11), f);
        fea[c] = f;
        float4 a = Wcv[v][c];
        m0 = fmaf(a.x, f, m0);
        m1 = fmaf(a.y, f, m1);
        m2 = fmaf(a.z, f, m2);
        m3 = fmaf(a.w, f, m3);
    }

    float* op = out + (size_t)b * C_ * OH_ * OW_ + (size_t)oy * OW_ + ox;
    #pragma unroll
    for (int c = 0; c < 64; c++) {
        float4 bw = Wev[v][c];
        float acc = fea[c];
        acc = fmaf(bw.x, m0, acc);
        acc = fmaf(bw.y, m1, acc);
        acc = fmaf(bw.z, m2, acc);
        acc = fmaf(bw.w, m3, acc);
        op[(size_t)c * (OH_ * OW_)] = acc;
    }
}

extern "C" void kernel_launch(void* const* d_in, const int* in_sizes, int n_in,
                              void* d_out, int out_size) {
    const float* x    = (const float*)d_in[0];
    const float* wc   = (const float*)d_in[1];
    const float* we   = (const float*)d_in[2];
    const float* w1   = (const float*)d_in[3];
    const float* b1   = (const float*)d_in[4];
    const float* w2   = (const float*)d_in[5];
    const float* b2   = (const float*)d_in[6];
    const float* rww  = (const float*)d_in[7];
    const float* rwb  = (const float*)d_in[8];
    const float* ofw  = (const float*)d_in[9];
    const float* ofb  = (const float*)d_in[10];
    float* out = (float*)d_out;

    prep_kernel<<<1, 256>>>(wc, we, w1, b1, w2, b2, rww, rwb, ofw, ofb);

    dim3 grid(3, OH_, B_);
    upsample_kernel<<<grid, 128>>>(x, out);
}